// round 9
// baseline (speedup 1.0000x reference)
#include <cuda_runtime.h>
#include <math.h>
#include <stdint.h>

#define HH    64
#define DIMC  512     // per-axis sinusoid width
#define ODIM  256     // output dim
#define BATCH 8
#define NSPLIT 16     // split-K chunks (32 k each)

// C[r][o]: r<64 -> A[h][o] (W cols 0:512), r>=64 -> B[w][o] (W cols 512:1024).
// Static-zero at load; k2's ticket epilogue re-zeroes it after every use, so
// each launch (correctness run, capture, every replay) sees C == 0 on entry.
__device__ float        g_C[2 * HH][ODIM];
__device__ unsigned int g_end_cnt;    // k2 exit tickets (reset by last block)

// ---------------------------------------------------------------------------
// k1: fused embed + split-K GEMM, REDG accumulation into g_C.
//   C[half*64+m][o] += sum_{k in chunk} embed(m)[k] * W[o][half*512+k]
// grid (16 kc, 4 ntiles, 2 halves) = 128 blocks x 256 threads.
// Inner loop: 2x LDS.128 per 16 FMA (Et transposed to [k][m]).
// ---------------------------------------------------------------------------
__global__ __launch_bounds__(256) void k1_embed_gemm(const float* __restrict__ W) {
    const int kc   = blockIdx.x;
    const int k0   = kc * 32;
    const int n0   = blockIdx.y * 64;
    const int half = blockIdx.z;
    const int off  = half * DIMC;

    __shared__ float fr[32];
    __shared__ float Et[32][68];    // [k][m] transposed embed tile, padded
    __shared__ float Ws[32][68];    // [k][n] padded, float4-aligned rows

    const int t = threadIdx.x;

    if (t < 32) {
        int c = k0 + t;
        float expo = (c < 256) ? (float)(2 * c + 1) * (1.0f / 512.0f)
                               : (float)(2 * (c - 256)) * (1.0f / 512.0f);
        fr[t] = __expf(-expo * 6.907755278982137f);   // 1000^(-expo)
    }
    __syncthreads();

    // embed tile transposed: Et[kk][m], coalesced over m
    #pragma unroll
    for (int e = t; e < 32 * 64; e += 256) {
        int m = e & 63, kk = e >> 6;
        float zf = (float)m * fr[kk];
        Et[kk][m] = (k0 + kk < 256) ? __sinf(zf) : __cosf(zf);
    }
    // stage W tile (transposed): rows n0..n0+63, cols k0..k0+31, coalesced over k
    #pragma unroll
    for (int e = t; e < 64 * 32; e += 256) {
        int kk = e & 31, i = e >> 5;
        Ws[kk][i] = W[(size_t)(n0 + i) * (2 * DIMC) + off + k0 + kk];
    }
    __syncthreads();

    const int tx = t & 15, ty = t >> 4;    // 16 x 16 threads
    const int mb = ty * 4, nb = tx * 4;    // 4x4 micro-tile

    float acc[4][4] = {};
    #pragma unroll 8
    for (int k = 0; k < 32; k++) {
        float4 a = *(const float4*)&Et[k][mb];   // 4 m-values
        float4 b = *(const float4*)&Ws[k][nb];   // 4 n-values
        acc[0][0] += a.x * b.x; acc[0][1] += a.x * b.y; acc[0][2] += a.x * b.z; acc[0][3] += a.x * b.w;
        acc[1][0] += a.y * b.x; acc[1][1] += a.y * b.y; acc[1][2] += a.y * b.z; acc[1][3] += a.y * b.w;
        acc[2][0] += a.z * b.x; acc[2][1] += a.z * b.y; acc[2][2] += a.z * b.z; acc[2][3] += a.z * b.w;
        acc[3][0] += a.w * b.x; acc[3][1] += a.w * b.y; acc[3][2] += a.w * b.z; acc[3][3] += a.w * b.w;
    }

    const int rbase = half * 64 + mb;
    #pragma unroll
    for (int i = 0; i < 4; i++)
        #pragma unroll
        for (int j = 0; j < 4; j++)
            atomicAdd(&g_C[rbase + i][n0 + nb + j], acc[i][j]);   // REDG, distinct addrs
}

// ---------------------------------------------------------------------------
// k2: broadcast write, read-amortized.
//   out[b][h][w][o] = C[h][o] + C[64+w][o]
// block (h, wq): h fixed, w in [wq*16, wq*16+16), ALL 8 batches.
// Reads 17 KB of C per block -> total C reads 4.4 MB; writes 33.5 MB.
// grid (64, 4) = 256 blocks x 256 threads; 32 coalesced STG.128 per thread.
// Epilogue: last-arriving block re-zeroes g_C for the next replay.
// ---------------------------------------------------------------------------
__global__ __launch_bounds__(256) void k2_write(float* __restrict__ out) {
    const int t  = threadIdx.x;
    const int q  = t & 63;        // float4 column (o = 4q)
    const int rg = t >> 6;        // 0..3 -> 4 w-rows each
    const int h  = blockIdx.x;    // 0..63
    const int wq = blockIdx.y;    // 0..3

    const size_t colo = (size_t)q * 4;
    float4 a = *(const float4*)&g_C[h][colo];

    #pragma unroll
    for (int i = 0; i < 4; i++) {
        int w = wq * 16 + rg * 4 + i;
        float4 e = *(const float4*)&g_C[64 + w][colo];
        float4 v;
        v.x = a.x + e.x; v.y = a.y + e.y; v.z = a.z + e.z; v.w = a.w + e.w;

        size_t base = (((size_t)h * HH + w) * ODIM) + colo;
        const size_t bstride = (size_t)HH * HH * ODIM;
        #pragma unroll
        for (int b = 0; b < BATCH; b++)
            *(float4*)&out[base + (size_t)b * bstride] = v;
    }

    // ---- epilogue: last block (all 256 have finished reading g_C) zeroes it
    __syncthreads();
    __shared__ unsigned int ticket;
    if (t == 0) ticket = atomicAdd(&g_end_cnt, 1u);
    __syncthreads();

    if (ticket == (unsigned)(HH * 4 - 1)) {
        float4 z4 = make_float4(0.f, 0.f, 0.f, 0.f);
        float4* cp = (float4*)g_C;
        #pragma unroll
        for (int i = t; i < (2 * HH * ODIM) / 4; i += 256)
            cp[i] = z4;
        if (t == 0) g_end_cnt = 0;   // ordered vs next launch by kernel boundary
    }
}

// ---------------------------------------------------------------------------
extern "C" void kernel_launch(void* const* d_in, const int* in_sizes, int n_in,
                              void* d_out, int out_size) {
    const float* W = (const float*)d_in[0];   // W_im: (256, 1024) fp32
    float* out = (float*)d_out;               // (8, 64, 64, 256, 1) fp32

    dim3 g1(NSPLIT, 4, 2);
    k1_embed_gemm<<<g1, 256>>>(W);
    dim3 g2(HH, 4);
    k2_write<<<g2, 256>>>(out);
}